// round 1
// baseline (speedup 1.0000x reference)
#include <cuda_runtime.h>

// Problem constants
#define DIM   512
#define NH    8
#define DH    64          // DIM / NH
#define NLAT  128
#define NTOK  16
#define BATCH 1024        // TRUE_BATCH * NUM_LATENTS = 8 * 128
#define MQ    (BATCH * NTOK)    // 16384 query rows
#define MKV   (BATCH * NLAT)    // 131072 latent rows

// Scratch (static __device__ arrays: allowed; no allocations anywhere)
__device__ float g_q  [MQ  * DIM];   //  33.5 MB
__device__ float g_k  [MKV * DIM];   // 268 MB (only j <= b%128 rows valid/used)
__device__ float g_v  [MKV * DIM];   // 268 MB
__device__ float g_att[MQ  * DIM];   //  33.5 MB

// ---------------------------------------------------------------------------
// Generic C = A @ W^T (+ optional bias).  A: (M,512) row-major, W: (512,512)
// row-major (so C[m,n] = sum_k A[m,k] * W[n,k]).  BM=128, BN=64, BK=16.
// 256 threads, each computes an 8x4 register tile (two 4-row chunks).
// Grid: (512/64, M/128)
// ---------------------------------------------------------------------------
__global__ __launch_bounds__(256) void gemm128(const float* __restrict__ A,
                                               const float* __restrict__ W,
                                               const float* __restrict__ bias,
                                               float* __restrict__ C)
{
    __shared__ float As[16][128];
    __shared__ float Ws[16][64];

    const int t   = threadIdx.x;
    const int bm  = blockIdx.y * 128;
    const int bn  = blockIdx.x * 64;
    const int tx4 = (t & 15) * 4;    // n offset (0..60)
    const int ty4 = (t >> 4) * 4;    // m offset (0..60), second chunk at +64

    const int ar  = t >> 2;          // 0..63
    const int ac4 = (t & 3) * 4;     // 0,4,8,12

    float acc[8][4];
#pragma unroll
    for (int i = 0; i < 8; i++)
#pragma unroll
        for (int j = 0; j < 4; j++) acc[i][j] = 0.f;

    for (int kt = 0; kt < DIM; kt += 16) {
        // Load A tile (128x16): two float4 per thread
        float4 a0 = *(const float4*)&A[(size_t)(bm + ar)      * DIM + kt + ac4];
        float4 a1 = *(const float4*)&A[(size_t)(bm + ar + 64) * DIM + kt + ac4];
        // Load W tile (64x16): one float4 per thread (rows bn..bn+63)
        float4 w0 = *(const float4*)&W[(size_t)(bn + ar) * DIM + kt + ac4];

        As[ac4 + 0][ar] = a0.x; As[ac4 + 1][ar] = a0.y;
        As[ac4 + 2][ar] = a0.z; As[ac4 + 3][ar] = a0.w;
        As[ac4 + 0][ar + 64] = a1.x; As[ac4 + 1][ar + 64] = a1.y;
        As[ac4 + 2][ar + 64] = a1.z; As[ac4 + 3][ar + 64] = a1.w;
        Ws[ac4 + 0][ar] = w0.x; Ws[ac4 + 1][ar] = w0.y;
        Ws[ac4 + 2][ar] = w0.z; Ws[ac4 + 3][ar] = w0.w;
        __syncthreads();

#pragma unroll
        for (int k = 0; k < 16; k++) {
            float4 va0 = *(const float4*)&As[k][ty4];
            float4 va1 = *(const float4*)&As[k][64 + ty4];
            float4 vw  = *(const float4*)&Ws[k][tx4];
            float am[8] = {va0.x, va0.y, va0.z, va0.w, va1.x, va1.y, va1.z, va1.w};
            float wn[4] = {vw.x, vw.y, vw.z, vw.w};
#pragma unroll
            for (int mi = 0; mi < 8; mi++)
#pragma unroll
                for (int ni = 0; ni < 4; ni++)
                    acc[mi][ni] += am[mi] * wn[ni];
        }
        __syncthreads();
    }

    float4 bb = make_float4(0.f, 0.f, 0.f, 0.f);
    if (bias) bb = *(const float4*)&bias[bn + tx4];

#pragma unroll
    for (int mm = 0; mm < 4; mm++) {
        float4 o0 = make_float4(acc[mm][0] + bb.x, acc[mm][1] + bb.y,
                                acc[mm][2] + bb.z, acc[mm][3] + bb.w);
        *(float4*)&C[(size_t)(bm + ty4 + mm) * DIM + bn + tx4] = o0;
        float4 o1 = make_float4(acc[4 + mm][0] + bb.x, acc[4 + mm][1] + bb.y,
                                acc[4 + mm][2] + bb.z, acc[4 + mm][3] + bb.w);
        *(float4*)&C[(size_t)(bm + 64 + ty4 + mm) * DIM + bn + tx4] = o1;
    }
}

// ---------------------------------------------------------------------------
// Fused K + V projection with mask-based row skipping.
// Virtual N' = 1024: n < 512 -> K = l @ Wk^T, else V = l @ Wv^T.
// BM=64 so a tile lives entirely inside one batch element (128 rows/batch);
// blocks whose 64-row slab is fully beyond limit = b%128 exit immediately.
// Grid: (1024/64 = 16, 131072/64 = 2048)
// ---------------------------------------------------------------------------
__global__ __launch_bounds__(256) void gemm_kv(const float* __restrict__ L,
                                               const float* __restrict__ Wk,
                                               const float* __restrict__ Wv)
{
    const int bm    = blockIdx.y * 64;
    const int b     = bm >> 7;        // batch element
    const int j0    = bm & 127;       // 0 or 64
    const int limit = b & 127;        // b % 128
    if (j0 > limit) return;           // whole tile masked out -> never read

    const int bnv = blockIdx.x * 64;
    const float* __restrict__ W;
    float* __restrict__ Cout;
    int bn;
    if (bnv < 512) { W = Wk; Cout = g_k; bn = bnv; }
    else           { W = Wv; Cout = g_v; bn = bnv - 512; }

    __shared__ float As[16][64];
    __shared__ float Ws[16][64];

    const int t   = threadIdx.x;
    const int tx4 = (t & 15) * 4;
    const int ty4 = (t >> 4) * 4;
    const int ar  = t >> 2;           // 0..63
    const int ac4 = (t & 3) * 4;

    float acc[4][4];
#pragma unroll
    for (int i = 0; i < 4; i++)
#pragma unroll
        for (int j = 0; j < 4; j++) acc[i][j] = 0.f;

    for (int kt = 0; kt < DIM; kt += 16) {
        float4 a0 = *(const float4*)&L[(size_t)(bm + ar) * DIM + kt + ac4];
        float4 w0 = *(const float4*)&W[(size_t)(bn + ar) * DIM + kt + ac4];
        As[ac4 + 0][ar] = a0.x; As[ac4 + 1][ar] = a0.y;
        As[ac4 + 2][ar] = a0.z; As[ac4 + 3][ar] = a0.w;
        Ws[ac4 + 0][ar] = w0.x; Ws[ac4 + 1][ar] = w0.y;
        Ws[ac4 + 2][ar] = w0.z; Ws[ac4 + 3][ar] = w0.w;
        __syncthreads();

#pragma unroll
        for (int k = 0; k < 16; k++) {
            float4 va = *(const float4*)&As[k][ty4];
            float4 vw = *(const float4*)&Ws[k][tx4];
            float am[4] = {va.x, va.y, va.z, va.w};
            float wn[4] = {vw.x, vw.y, vw.z, vw.w};
#pragma unroll
            for (int mi = 0; mi < 4; mi++)
#pragma unroll
                for (int ni = 0; ni < 4; ni++)
                    acc[mi][ni] += am[mi] * wn[ni];
        }
        __syncthreads();
    }

#pragma unroll
    for (int mm = 0; mm < 4; mm++) {
        int j = j0 + ty4 + mm;
        if (j <= limit) {
            float4 o = make_float4(acc[mm][0], acc[mm][1], acc[mm][2], acc[mm][3]);
            *(float4*)&Cout[(size_t)(bm + ty4 + mm) * DIM + bn + tx4] = o;
        }
    }
}

// ---------------------------------------------------------------------------
// Attention: one block per (b, h); 128 threads.
// q(16,64) in smem; scores only for j <= b%128; softmax; P @ V -> g_att.
// Grid: (1024, 8)
// ---------------------------------------------------------------------------
__global__ __launch_bounds__(128) void attn_kernel()
{
    const int b = blockIdx.x;
    const int h = blockIdx.y;
    const int t = threadIdx.x;
    const int limit = b & 127;
    const int nj = limit + 1;

    __shared__ float qs[NTOK][DH + 1];    // +1 pad: conflict-free column reads
    __shared__ float ps[NTOK][NLAT + 1];  // +1 pad: conflict-free row scans

    // Load Q tile (16 x 64)
#pragma unroll
    for (int u = 0; u < 8; u++) {
        int e = t + u * 128;              // 0..1023
        int row = e >> 6, d = e & 63;
        qs[row][d] = g_q[(size_t)(b * NTOK + row) * DIM + h * DH + d];
    }
    __syncthreads();

    // Scores: thread -> (i = t&15, j stripe = t>>4)
    {
        const int i = t & 15;
        const int jg = t >> 4;            // 0..7
        for (int j = jg; j < nj; j += 8) {
            const float4* k4 = (const float4*)&g_k[(size_t)(b * NLAT + j) * DIM + h * DH];
            float s = 0.f;
#pragma unroll
            for (int d4 = 0; d4 < 16; d4++) {
                float4 kk = k4[d4];
                s += qs[i][d4 * 4 + 0] * kk.x + qs[i][d4 * 4 + 1] * kk.y
                   + qs[i][d4 * 4 + 2] * kk.z + qs[i][d4 * 4 + 3] * kk.w;
            }
            ps[i][j] = s * 0.125f;        // dh^-0.5 = 1/8
        }
    }
    __syncthreads();

    // Softmax per row (threads 0..15, one row each)
    if (t < NTOK) {
        float m = -1e30f;
        for (int j = 0; j < nj; j++) m = fmaxf(m, ps[t][j]);
        float s = 0.f;
        for (int j = 0; j < nj; j++) { float e = expf(ps[t][j] - m); ps[t][j] = e; s += e; }
        float inv = 1.f / s;
        for (int j = 0; j < nj; j++) ps[t][j] *= inv;
    }
    __syncthreads();

    // Out = P @ V.  thread -> d = t&63, i base = t>>6; 8 rows per thread in regs.
    {
        const int d  = t & 63;
        const int i0 = t >> 6;            // 0 or 1
        float acc[8];
#pragma unroll
        for (int ii = 0; ii < 8; ii++) acc[ii] = 0.f;
        for (int j = 0; j < nj; j++) {
            float vv = g_v[(size_t)(b * NLAT + j) * DIM + h * DH + d];
#pragma unroll
            for (int ii = 0; ii < 8; ii++)
                acc[ii] += ps[i0 + 2 * ii][j] * vv;
        }
#pragma unroll
        for (int ii = 0; ii < 8; ii++) {
            int i = i0 + 2 * ii;
            g_att[(size_t)(b * NTOK + i) * DIM + h * DH + d] = acc[ii];
        }
    }
}

// ---------------------------------------------------------------------------
extern "C" void kernel_launch(void* const* d_in, const int* in_sizes, int n_in,
                              void* d_out, int out_size)
{
    const float* x  = (const float*)d_in[0];
    const float* l  = (const float*)d_in[1];
    const float* Wq = (const float*)d_in[2];
    const float* Wk = (const float*)d_in[3];
    const float* Wv = (const float*)d_in[4];
    const float* Wo = (const float*)d_in[5];
    const float* bo = (const float*)d_in[6];
    float* out = (float*)d_out;

    float *pq, *pa;
    cudaGetSymbolAddress((void**)&pq, g_q);
    cudaGetSymbolAddress((void**)&pa, g_att);

    // 1) Q projection: (16384,512) @ Wq^T
    gemm128<<<dim3(8, MQ / 128), 256>>>(x, Wq, nullptr, pq);
    // 2) Fused K+V projection with mask row skipping
    gemm_kv<<<dim3(16, MKV / 64), 256>>>(l, Wk, Wv);
    // 3) Attention per (b, h)
    attn_kernel<<<dim3(BATCH, NH), 128>>>();
    // 4) Output projection + bias
    gemm128<<<dim3(8, MQ / 128), 256>>>(pa, Wo, bo, out);
}